// round 16
// baseline (speedup 1.0000x reference)
#include <cuda_runtime.h>
#include <math.h>
#include <stdint.h>

#define GX 200
#define GY 200
#define GZ 16
#define NVOX (GX*GY*GZ)
#define NCOL (GX*GY)          // 40000 xy columns
#define F_N 8
#define G_MAX 32768
#define CAP 32                // per-(column,slab) entries (mean ~11)

__device__ int    g_count[NCOL * 2];                // [col][slab]
__device__ float4 g_entries[NCOL * 2 * CAP + 1];    // +1 pad for prefetch
__device__ float4 g_feats[G_MAX * 2];
__device__ float4 g_setup[G_MAX * 3];               // s0:{mx,my,mz,l2op} s1:{a00,a01,a11,a02} s2:{a12,a22,bbox,pk}

__device__ __forceinline__ float ex2f(float x) {
    float r; asm("ex2.approx.f32 %0, %1;" : "=f"(r) : "f"(x)); return r;
}

// ---------- Pass 0: per-gaussian setup (1 thread/gaussian) ----------
__global__ void gv_setup_kernel(const float* __restrict__ means,
                                const float* __restrict__ opac,
                                const float* __restrict__ cov,
                                const float* __restrict__ feat,
                                int G) {
    int g = blockIdx.x * blockDim.x + threadIdx.x;
    if (g >= G || g >= G_MAX) return;

    const float lox = -40.f, loy = -40.f, loz = -1.f;
    const float hix =  40.f, hiy =  40.f, hiz =  5.4f;
    const float VOX = 0.4f;

    float mx = means[g*3 + 0];
    float my = means[g*3 + 1];
    float mz = means[g*3 + 2];
    const float* C = cov + (size_t)g * 9;
    float c00 = C[0], c01 = C[1], c02 = C[2];
    float c11 = C[4], c12 = C[5], c22 = C[8];

    const float4* fv = (const float4*)(feat + (size_t)g * F_N);
    g_feats[g*2 + 0] = fv[0];
    g_feats[g*2 + 1] = fv[1];

    float sx = sqrtf(c00), sy = sqrtf(c11), sz = sqrtf(c22);
    float blx = mx - 3.f*sx, bly = my - 3.f*sy, blz = mz - 3.f*sz;
    float bhx = mx + 3.f*sx, bhy = my + 3.f*sy, bhz = mz + 3.f*sz;

    bool valid = (bhx > lox) && (bhy > loy) && (bhz > loz) &&
                 (blx < hix) && (bly < hiy) && (blz < hiz);
    if (!valid) {
        g_setup[g*3 + 2] = make_float4(0.f, 0.f, 0.f, __uint_as_float(0u));
        return;
    }

    // symmetric 3x3 inverse
    float i00 = c11*c22 - c12*c12;
    float i01 = c02*c12 - c01*c22;
    float i02 = c01*c12 - c02*c11;
    float i11 = c00*c22 - c02*c02;
    float i12 = c01*c02 - c00*c12;
    float i22 = c00*c11 - c01*c01;
    float det = c00*i00 + c01*i01 + c02*i02;
    float rdet = 1.f / det;
    float a00 = i00*rdet, a01 = i01*rdet, a02 = i02*rdet;
    float a11 = i11*rdet, a12 = i12*rdet, a22 = i22*rdet;

    float blxc = fminf(fmaxf(blx, lox), hix);
    float blyc = fminf(fmaxf(bly, loy), hiy);
    float blzc = fminf(fmaxf(blz, loz), hiz);
    float bhxc = fminf(fmaxf(bhx, lox), hix);
    float bhyc = fminf(fmaxf(bhy, loy), hiy);
    float bhzc = fminf(fmaxf(bhz, loz), hiz);

    int ilox = min((int)((blxc - lox) / VOX), GX - 1);
    int iloy = min((int)((blyc - loy) / VOX), GY - 1);
    int iloz = min((int)((blzc - loz) / VOX), GZ - 1);
    int ihix = min((int)((bhxc - lox) / VOX), GX - 1);
    int ihiy = min((int)((bhyc - loy) / VOX), GY - 1);
    int ihiz = min((int)((bhzc - loz) / VOX), GZ - 1);

    int nx = ihix - ilox + 1;
    int ny = ihiy - iloy + 1;

    float op = opac[g];
    float l2op = (op > 0.f) ? log2f(op) : -127.f;

    unsigned zmask = (0xFFFFu << iloz) & (0xFFFFu >> (15 - ihiz));
    unsigned pk = (unsigned)g | (zmask << 15);
    unsigned bb = (unsigned)ilox | ((unsigned)iloy << 8) |
                  ((unsigned)nx << 16) | ((unsigned)ny << 24);

    g_setup[g*3 + 0] = make_float4(mx, my, mz, l2op);
    g_setup[g*3 + 1] = make_float4(a00, a01, a11, a02);
    g_setup[g*3 + 2] = make_float4(a12, a22, __uint_as_float(bb), __uint_as_float(pk));
}

// ---------- Pass 1: bin (8 lanes/gaussian), per-(column,slab) lists ----------
__global__ void gv_bin_kernel(int G) {
    int g = (blockIdx.x * blockDim.x + threadIdx.x) >> 3;
    if (g >= G || g >= G_MAX) return;
    int sub = threadIdx.x & 7;

    float4 s2 = g_setup[g*3 + 2];
    unsigned pk = __float_as_uint(s2.w);
    if (!pk) return;
    float4 s0 = g_setup[g*3 + 0];
    float4 s1 = g_setup[g*3 + 1];

    const float lox = -40.f, loy = -40.f;
    const float VOX = 0.4f;
    const float NHL2E = -0.5f * 1.4426950408889634f;

    float mx = s0.x, my = s0.y, mz = s0.z, l2op = s0.w;
    float a00 = s1.x, a01 = s1.y, a11 = s1.z, a02 = s1.w;
    float a12 = s2.x, a22 = s2.y;
    unsigned bb = __float_as_uint(s2.z);
    int ilox = bb & 255, iloy = (bb >> 8) & 255;
    int nx = (bb >> 16) & 255, ny = (bb >> 24) & 255;

    unsigned zmask = (pk >> 15) & 0xFFFFu;
    bool slab0 = (zmask & 0x00FFu) != 0;
    bool slab1 = (zmask & 0xFF00u) != 0;

    float e2 = NHL2E * a22;                       // constant per gaussian
    float q1c = -2.f * a22 * mz;

    int ncols = nx * ny;
    for (int p = sub; p < ncols; p += 8) {
        int ox = p / ny;
        int oy = p - ox * ny;
        int ix = ilox + ox;
        int iy = iloy + oy;
        float dx = ((float)ix + 0.5f) * VOX + lox - mx;
        float dy = ((float)iy + 0.5f) * VOX + loy - my;
        float cxy = a00*dx*dx + a11*dy*dy + 2.f*a01*dx*dy;
        float L   = a02*dx + a12*dy;
        float q1 = 2.f*L + q1c;
        float q0 = cxy - 2.f*L*mz + a22*mz*mz;
        float e1 = NHL2E * q1;
        float e0 = NHL2E * q0 + l2op;

        int col = ix * GY + iy;
        float4 ent = make_float4(e0, e1, e2, __uint_as_float(pk));
        if (slab0) {
            int pos = atomicAdd(&g_count[col*2 + 0], 1);
            if (pos < CAP) g_entries[(size_t)(col*2 + 0) * CAP + pos] = ent;
        }
        if (slab1) {
            int pos = atomicAdd(&g_count[col*2 + 1], 1);
            if (pos < CAP) g_entries[(size_t)(col*2 + 1) * CAP + pos] = ent;
        }
    }
}

// ---------- Pass 2: 8 lanes/column, 2 z-voxels/thread, slab lists, prefetch ----------
__global__ void gv_gather_kernel(float* __restrict__ out) {
    int tid = blockIdx.x * blockDim.x + threadIdx.x;
    int col = tid >> 3;
    if (col >= NCOL) return;
    int zs = (tid & 7) << 1;           // z pair {zs, zs+1}
    int slab = zs >> 3;

    const float loz = -1.f;
    const float VOX = 0.4f;
    float wz0 = ((float)zs + 0.5f) * VOX + loz;
    float wz1 = wz0 + VOX;

    int lidx = col*2 + slab;
    int n = min(g_count[lidx], CAP);
    const float4* elist = g_entries + (size_t)lidx * CAP;

    float dens0 = 0.f, dens1 = 0.f;
    float p0 = 0.f, p1 = 0.f, p2 = 0.f, p3 = 0.f, p4 = 0.f, p5 = 0.f, p6 = 0.f, p7 = 0.f;
    float r0 = 0.f, r1 = 0.f, r2 = 0.f, r3 = 0.f, r4 = 0.f, r5 = 0.f, r6 = 0.f, r7 = 0.f;

    float4 q = elist[0];
    for (int e = 0; e < n; e++) {
        float4 qn = elist[e + 1];        // pad makes this safe
        unsigned pk = __float_as_uint(q.w);
        unsigned m2 = (pk >> (15 + zs)) & 3u;
        if (m2) {
            float ev0 = (m2 & 1u) ? ex2f(q.x + wz0 * (q.y + q.z * wz0)) : 0.f;
            float ev1 = (m2 & 2u) ? ex2f(q.x + wz1 * (q.y + q.z * wz1)) : 0.f;

            int gid = pk & 0x7FFF;
            float4 f0 = g_feats[gid*2 + 0];
            float4 f1 = g_feats[gid*2 + 1];
            dens0 += ev0; dens1 += ev1;
            p0 += ev0*f0.x; p1 += ev0*f0.y; p2 += ev0*f0.z; p3 += ev0*f0.w;
            p4 += ev0*f1.x; p5 += ev0*f1.y; p6 += ev0*f1.z; p7 += ev0*f1.w;
            r0 += ev1*f0.x; r1 += ev1*f0.y; r2 += ev1*f0.z; r3 += ev1*f0.w;
            r4 += ev1*f1.x; r5 += ev1*f1.y; r6 += ev1*f1.z; r7 += ev1*f1.w;
        }
        q = qn;
    }

    int vox = col * GZ + zs;
    out[vox]     = dens0;
    out[vox + 1] = dens1;
    float s0 = 1.f / fmaxf(dens0, 1e-6f);
    float s1 = 1.f / fmaxf(dens1, 1e-6f);
    float4* fp = (float4*)(out + NVOX) + (size_t)vox * 2;
    fp[0] = make_float4(p0*s0, p1*s0, p2*s0, p3*s0);
    fp[1] = make_float4(p4*s0, p5*s0, p6*s0, p7*s0);
    fp[2] = make_float4(r0*s1, r1*s1, r2*s1, r3*s1);
    fp[3] = make_float4(r4*s1, r5*s1, r6*s1, r7*s1);
}

extern "C" void kernel_launch(void* const* d_in, const int* in_sizes, int n_in,
                              void* d_out, int out_size) {
    const float* means = (const float*)d_in[0];   // (G,3)
    const float* opac  = (const float*)d_in[1];   // (G,1)
    const float* cov   = (const float*)d_in[2];   // (G,3,3)
    const float* feat  = (const float*)d_in[3];   // (G,8)
    float* out = (float*)d_out;                   // [640000 density | 5120000 feats]

    int G = in_sizes[0] / 3;

    void* cnt_ptr = nullptr;
    cudaGetSymbolAddress(&cnt_ptr, g_count);
    cudaMemsetAsync(cnt_ptr, 0, NCOL * 2 * sizeof(int));

    gv_setup_kernel<<<(G + 255) / 256, 256>>>(means, opac, cov, feat, G);
    gv_bin_kernel<<<(G * 8 + 255) / 256, 256>>>(G);

    int gthreads = NCOL * 8;   // 320,000
    gv_gather_kernel<<<(gthreads + 255) / 256, 256>>>(out);
}

// round 17
// speedup vs baseline: 1.0355x; 1.0355x over previous
#include <cuda_runtime.h>
#include <math.h>
#include <stdint.h>

#define GX 200
#define GY 200
#define GZ 16
#define NVOX (GX*GY*GZ)
#define NCOL (GX*GY)          // 40000 xy columns
#define F_N 8
#define G_MAX 32768
#define CAP 32                // per-(column,slab) entries (slab mean ~11)

__device__ int    g_count[NCOL * 2];                // [col][slab]
__device__ float4 g_entries[NCOL * 2 * CAP + 1];    // +1 pad for prefetch
__device__ float4 g_feats[G_MAX * 2];

__device__ __forceinline__ float ex2f(float x) {
    float r; asm("ex2.approx.f32 %0, %1;" : "=f"(r) : "f"(x)); return r;
}
__device__ __forceinline__ uint64_t pack2(float lo, float hi) {
    uint64_t r; asm("mov.b64 %0, {%1, %2};" : "=l"(r) : "f"(lo), "f"(hi)); return r;
}
__device__ __forceinline__ void unpack2(float& lo, float& hi, uint64_t v) {
    asm("mov.b64 {%0, %1}, %2;" : "=f"(lo), "=f"(hi) : "l"(v));
}
__device__ __forceinline__ uint64_t fma2(uint64_t a, uint64_t b, uint64_t c) {
    uint64_t o; asm("fma.rn.f32x2 %0, %1, %2, %3;" : "=l"(o) : "l"(a), "l"(b), "l"(c)); return o;
}
__device__ __forceinline__ uint64_t add2(uint64_t a, uint64_t b) {
    uint64_t o; asm("add.rn.f32x2 %0, %1, %2;" : "=l"(o) : "l"(a), "l"(b)); return o;
}

// ---------- Pass 1: bin, 8 lanes per gaussian, per-(column,slab) lists ----------
__global__ void gv_bin_kernel(const float* __restrict__ means,
                              const float* __restrict__ opac,
                              const float* __restrict__ cov,
                              const float* __restrict__ feat,
                              int G) {
    int g = (blockIdx.x * blockDim.x + threadIdx.x) >> 3;
    if (g >= G || g >= G_MAX) return;
    int sub = threadIdx.x & 7;

    const float lox = -40.f, loy = -40.f, loz = -1.f;
    const float hix =  40.f, hiy =  40.f, hiz =  5.4f;
    const float VOX = 0.4f;
    const float NHL2E = -0.5f * 1.4426950408889634f;   // -0.5 * log2(e)

    float mx = means[g*3 + 0];
    float my = means[g*3 + 1];
    float mz = means[g*3 + 2];
    const float* C = cov + (size_t)g * 9;
    float c00 = C[0], c01 = C[1], c02 = C[2];
    float c11 = C[4], c12 = C[5], c22 = C[8];

    const float4* fv = (const float4*)(feat + (size_t)g * F_N);
    if (sub == 0) g_feats[g*2 + 0] = fv[0];
    if (sub == 1) g_feats[g*2 + 1] = fv[1];

    float sx = sqrtf(c00), sy = sqrtf(c11), sz = sqrtf(c22);
    float blx = mx - 3.f*sx, bly = my - 3.f*sy, blz = mz - 3.f*sz;
    float bhx = mx + 3.f*sx, bhy = my + 3.f*sy, bhz = mz + 3.f*sz;

    bool valid = (bhx > lox) && (bhy > loy) && (bhz > loz) &&
                 (blx < hix) && (bly < hiy) && (blz < hiz);
    if (!valid) return;

    // symmetric 3x3 inverse
    float i00 = c11*c22 - c12*c12;
    float i01 = c02*c12 - c01*c22;
    float i02 = c01*c12 - c02*c11;
    float i11 = c00*c22 - c02*c02;
    float i12 = c01*c02 - c00*c12;
    float i22 = c00*c11 - c01*c01;
    float det = c00*i00 + c01*i01 + c02*i02;
    float rdet = 1.f / det;
    float a00 = i00*rdet, a01 = i01*rdet, a02 = i02*rdet;
    float a11 = i11*rdet, a12 = i12*rdet, a22 = i22*rdet;

    float blxc = fminf(fmaxf(blx, lox), hix);
    float blyc = fminf(fmaxf(bly, loy), hiy);
    float blzc = fminf(fmaxf(blz, loz), hiz);
    float bhxc = fminf(fmaxf(bhx, lox), hix);
    float bhyc = fminf(fmaxf(bhy, loy), hiy);
    float bhzc = fminf(fmaxf(bhz, loz), hiz);

    int ilox = min((int)((blxc - lox) / VOX), GX - 1);
    int iloy = min((int)((blyc - loy) / VOX), GY - 1);
    int iloz = min((int)((blzc - loz) / VOX), GZ - 1);
    int ihix = min((int)((bhxc - lox) / VOX), GX - 1);
    int ihiy = min((int)((bhyc - loy) / VOX), GY - 1);
    int ihiz = min((int)((bhzc - loz) / VOX), GZ - 1);

    int nx = ihix - ilox + 1;
    int ny = ihiy - iloy + 1;

    float op = opac[g];
    float l2op = (op > 0.f) ? log2f(op) : -127.f;

    unsigned zmask = (0xFFFFu << iloz) & (0xFFFFu >> (15 - ihiz));
    unsigned pk = (unsigned)g | (zmask << 15);
    bool slab0 = (zmask & 0x00FFu) != 0;
    bool slab1 = (zmask & 0xFF00u) != 0;

    float e2  = NHL2E * a22;
    float q1c = -2.f * a22 * mz;

    int ncols = nx * ny;
    for (int p = sub; p < ncols; p += 8) {
        int ox = p / ny;
        int oy = p - ox * ny;
        int ix = ilox + ox;
        int iy = iloy + oy;
        float dx = ((float)ix + 0.5f) * VOX + lox - mx;
        float dy = ((float)iy + 0.5f) * VOX + loy - my;
        float cxy = a00*dx*dx + a11*dy*dy + 2.f*a01*dx*dy;
        float L   = a02*dx + a12*dy;
        float q1 = 2.f*L + q1c;
        float q0 = cxy - 2.f*L*mz + a22*mz*mz;
        float e1 = NHL2E * q1;
        float e0 = NHL2E * q0 + l2op;

        int col = ix * GY + iy;
        float4 ent = make_float4(e0, e1, e2, __uint_as_float(pk));
        if (slab0) {
            int pos = atomicAdd(&g_count[col*2 + 0], 1);
            if (pos < CAP) g_entries[(size_t)(col*2 + 0) * CAP + pos] = ent;
        }
        if (slab1) {
            int pos = atomicAdd(&g_count[col*2 + 1], 1);
            if (pos < CAP) g_entries[(size_t)(col*2 + 1) * CAP + pos] = ent;
        }
    }
}

// ---------- Pass 2: 8 lanes/column (4 per slab), 2 z-voxels/thread, fma2 accum ----------
__global__ void gv_gather_kernel(float* __restrict__ out) {
    int tid = blockIdx.x * blockDim.x + threadIdx.x;
    int col = tid >> 3;
    if (col >= NCOL) return;
    int zs = (tid & 7) << 1;           // z pair {zs, zs+1}
    int slab = zs >> 3;

    const float loz = -1.f;
    const float VOX = 0.4f;
    float wz0 = ((float)zs + 0.5f) * VOX + loz;
    float wz1 = wz0 + VOX;

    int lidx = col*2 + slab;
    int n = min(g_count[lidx], CAP);
    const float4* elist = g_entries + (size_t)lidx * CAP;

    uint64_t D   = 0;                   // (dens0, dens1)
    uint64_t A01 = 0, A23 = 0, A45 = 0, A67 = 0;   // voxel zs
    uint64_t B01 = 0, B23 = 0, B45 = 0, B67 = 0;   // voxel zs+1

    float4 q = elist[0];                // pad makes this safe even if n==0
    for (int e = 0; e < n; e++) {
        float4 qn = elist[e + 1];
        unsigned pk = __float_as_uint(q.w);
        unsigned m2 = (pk >> (15 + zs)) & 3u;
        if (m2) {
            float ev0 = (m2 & 1u) ? ex2f(q.x + wz0 * (q.y + q.z * wz0)) : 0.f;
            float ev1 = (m2 & 2u) ? ex2f(q.x + wz1 * (q.y + q.z * wz1)) : 0.f;

            int gid = pk & 0x7FFF;
            float4 f0 = g_feats[gid*2 + 0];
            float4 f1 = g_feats[gid*2 + 1];
            uint64_t f01 = pack2(f0.x, f0.y);
            uint64_t f23 = pack2(f0.z, f0.w);
            uint64_t f45 = pack2(f1.x, f1.y);
            uint64_t f67 = pack2(f1.z, f1.w);
            uint64_t e00 = pack2(ev0, ev0);
            uint64_t e11 = pack2(ev1, ev1);

            D   = add2(D, pack2(ev0, ev1));
            A01 = fma2(f01, e00, A01);
            A23 = fma2(f23, e00, A23);
            A45 = fma2(f45, e00, A45);
            A67 = fma2(f67, e00, A67);
            B01 = fma2(f01, e11, B01);
            B23 = fma2(f23, e11, B23);
            B45 = fma2(f45, e11, B45);
            B67 = fma2(f67, e11, B67);
        }
        q = qn;
    }

    float dens0, dens1;
    unpack2(dens0, dens1, D);

    int vox = col * GZ + zs;
    out[vox]     = dens0;
    out[vox + 1] = dens1;
    float s0 = 1.f / fmaxf(dens0, 1e-6f);
    float s1 = 1.f / fmaxf(dens1, 1e-6f);

    float a0,a1,a2,a3,a4,a5,a6,a7;
    unpack2(a0, a1, A01); unpack2(a2, a3, A23);
    unpack2(a4, a5, A45); unpack2(a6, a7, A67);
    float b0,b1,b2,b3,b4,b5,b6,b7;
    unpack2(b0, b1, B01); unpack2(b2, b3, B23);
    unpack2(b4, b5, B45); unpack2(b6, b7, B67);

    float4* fp = (float4*)(out + NVOX) + (size_t)vox * 2;
    fp[0] = make_float4(a0*s0, a1*s0, a2*s0, a3*s0);
    fp[1] = make_float4(a4*s0, a5*s0, a6*s0, a7*s0);
    fp[2] = make_float4(b0*s1, b1*s1, b2*s1, b3*s1);
    fp[3] = make_float4(b4*s1, b5*s1, b6*s1, b7*s1);
}

extern "C" void kernel_launch(void* const* d_in, const int* in_sizes, int n_in,
                              void* d_out, int out_size) {
    const float* means = (const float*)d_in[0];   // (G,3)
    const float* opac  = (const float*)d_in[1];   // (G,1)
    const float* cov   = (const float*)d_in[2];   // (G,3,3)
    const float* feat  = (const float*)d_in[3];   // (G,8)
    float* out = (float*)d_out;                   // [640000 density | 5120000 feats]

    int G = in_sizes[0] / 3;

    void* cnt_ptr = nullptr;
    cudaGetSymbolAddress(&cnt_ptr, g_count);
    cudaMemsetAsync(cnt_ptr, 0, NCOL * 2 * sizeof(int));

    gv_bin_kernel<<<(G * 8 + 255) / 256, 256>>>(means, opac, cov, feat, G);

    int gthreads = NCOL * 8;   // 320,000
    gv_gather_kernel<<<(gthreads + 255) / 256, 256>>>(out);
}